// round 1
// baseline (speedup 1.0000x reference)
#include <cuda_runtime.h>
#include <math.h>
#include <stdint.h>

#define Bb 16
#define Ss 4096
#define Dd 64
#define Hh 8
#define NB 64          // buckets per hash
#define NCHUNK 512     // Hh * NB
#define NEGV (-50000.0f)

// ---------------- device scratch (static globals: no runtime allocation) ----
__device__ int   g_bucket[Bb*Hh*Ss];     // local bucket id 0..63 per (b,h,t)
__device__ int   g_perm  [Bb*Hh*Ss];     // sorted rank -> t  (per (b,h) segment)
__device__ float g_o     [(size_t)Bb*Hh*Ss*Dd]; // per-hash outputs (128MB)
__device__ float g_logits[Bb*Hh*Ss];     // per-hash lse

// ---------------- 1) LSH hashing --------------------------------------------
// rot[b,h,t,i] = sum_f qk[b,t,f] * rotations[b,f,h,i]; bucket = argmax [rot,-rot]
#define TT 16
#define HASH_SMEM ((64*256 + TT*64) * 4)
__global__ void __launch_bounds__(256) hash_kernel(
    const float* __restrict__ qk, const float* __restrict__ rot)
{
    extern __shared__ float sm[];
    float* rotS = sm;              // [64][256]  (f major, hi = tid)
    float* qs   = sm + 64*256;     // [TT][64]

    int blocksPerB = Ss / TT;                 // 256
    int b  = blockIdx.x / blocksPerB;
    int t0 = (blockIdx.x % blocksPerB) * TT;
    int tid = threadIdx.x;

    const float* rb = rot + (size_t)b * 64 * 256;
    for (int f = 0; f < 64; f++)
        rotS[f*256 + tid] = rb[f*256 + tid];
    for (int idx = tid; idx < TT*64; idx += 256)
        qs[idx] = qk[((size_t)b*Ss + t0 + (idx >> 6))*Dd + (idx & 63)];
    __syncthreads();

    float acc[TT];
    #pragma unroll
    for (int i = 0; i < TT; i++) acc[i] = 0.f;
    for (int f = 0; f < 64; f++) {
        float rv = rotS[f*256 + tid];
        #pragma unroll
        for (int i = 0; i < TT; i++) acc[i] += qs[i*64 + f] * rv;
    }

    int lane = tid & 31;
    int h    = tid >> 5;            // warp w handles hash w
    #pragma unroll
    for (int i = 0; i < TT; i++) {
        float v = acc[i];
        float val; int idx;
        if (v >= -v) { val = v;  idx = lane; }        // tie (v==0) -> first idx
        else         { val = -v; idx = lane + 32; }
        #pragma unroll
        for (int m = 16; m > 0; m >>= 1) {
            float ov = __shfl_xor_sync(0xffffffffu, val, m);
            int   oi = __shfl_xor_sync(0xffffffffu, idx, m);
            if (ov > val || (ov == val && oi < idx)) { val = ov; idx = oi; }
        }
        if (lane == 0)
            g_bucket[((size_t)b*Hh + h)*Ss + t0 + i] = idx;
    }
}

// ---------------- 2) stable counting sort per (b,h) -------------------------
__global__ void __launch_bounds__(256) sort_kernel()
{
    __shared__ int sb[Ss];
    __shared__ int cnt[NB];
    __shared__ int offs[NB + 1];
    int bh  = blockIdx.x;           // b*Hh + h
    int tid = threadIdx.x;
    const int base = bh * Ss;

    for (int i = tid; i < NB; i += 256) cnt[i] = 0;
    __syncthreads();
    for (int i = tid; i < Ss; i += 256) {
        int v = g_bucket[base + i];
        sb[i] = v;
        atomicAdd(&cnt[v], 1);
    }
    __syncthreads();
    if (tid == 0) {
        offs[0] = 0;
        for (int k = 0; k < NB; k++) offs[k+1] = offs[k] + cnt[k];
    }
    __syncthreads();
    if (tid < NB) {                 // thread = bucket; stable in t order
        int w = tid, pos = offs[w];
        for (int t = 0; t < Ss; t++)
            if (sb[t] == w) g_perm[base + pos++] = t;
    }
}

// ---------------- 3) chunked attention + scatter ----------------------------
#define KS_STRIDE 65
#define P_STRIDE 129
#define ATTN_SMEM ((64*KS_STRIDE + 128*KS_STRIDE + 128*64) * 4 + 192 * 4)
__global__ void __launch_bounds__(256) attn_kernel(
    const float* __restrict__ qk, const float* __restrict__ v)
{
    extern __shared__ float sm[];
    float* qs = sm;                         // [64][65] raw q
    float* ks = qs + 64*KS_STRIDE;          // [128][65] normalized k; reused as probs[64][129]
    float* vs = ks + 128*KS_STRIDE;         // [128][64]
    int*   tq = (int*)(vs + 128*64);        // [64]
    int*   tk = tq + 64;                    // [128]

    int b = blockIdx.x >> 9;
    int c = blockIdx.x & (NCHUNK - 1);
    int h = c >> 6;
    int cprev = (c + NCHUNK - 1) & (NCHUNK - 1);
    int tid = threadIdx.x;
    const int pbase = b * (Hh * Ss);

    if (tid < 64) {
        tq[tid] = g_perm[pbase + c*64 + tid];
    } else if (tid < 192) {
        int j = tid - 64;
        tk[j] = (j < 64) ? g_perm[pbase + c*64 + j]
                         : g_perm[pbase + cprev*64 + (j - 64)];
    }
    __syncthreads();

    const float* qkb = qk + (size_t)b*Ss*Dd;
    const float* vb  = v  + (size_t)b*Ss*Dd;

    for (int idx = tid; idx < 64*16; idx += 256) {
        int r = idx >> 4, q4 = idx & 15;
        float4 x = *(const float4*)(qkb + (size_t)tq[r]*Dd + q4*4);
        float* d = qs + r*KS_STRIDE + q4*4;
        d[0]=x.x; d[1]=x.y; d[2]=x.z; d[3]=x.w;
    }
    for (int idx = tid; idx < 128*16; idx += 256) {
        int r = idx >> 4, q4 = idx & 15;
        float4 x = *(const float4*)(qkb + (size_t)tk[r]*Dd + q4*4);
        float* d = ks + r*KS_STRIDE + q4*4;
        d[0]=x.x; d[1]=x.y; d[2]=x.z; d[3]=x.w;
        float4 y = *(const float4*)(vb + (size_t)tk[r]*Dd + q4*4);
        *(float4*)(vs + r*64 + q4*4) = y;
    }
    __syncthreads();

    // normalize k rows (make_unit_length: x / (||x|| + 1e-6))
    if (tid < 128) {
        float ssq = 0.f;
        float* row = ks + tid*KS_STRIDE;
        #pragma unroll
        for (int f = 0; f < 64; f++) ssq += row[f]*row[f];
        float inv = 1.0f / (sqrtf(ssq) + 1e-6f);
        #pragma unroll
        for (int f = 0; f < 64; f++) row[f] *= inv;
    }
    __syncthreads();

    // dots[64][128]: thread (rt,ct) owns rows 4rt+a, cols ct+16*jj
    int rt = tid >> 4;
    int ct = tid & 15;
    float dacc[4][8];
    #pragma unroll
    for (int a = 0; a < 4; a++)
        #pragma unroll
        for (int jj = 0; jj < 8; jj++) dacc[a][jj] = 0.f;

    for (int f = 0; f < 64; f++) {
        float qv[4];
        #pragma unroll
        for (int a = 0; a < 4; a++) qv[a] = qs[(4*rt + a)*KS_STRIDE + f];
        #pragma unroll
        for (int jj = 0; jj < 8; jj++) {
            float kv = ks[(ct + 16*jj)*KS_STRIDE + f];
            #pragma unroll
            for (int a = 0; a < 4; a++) dacc[a][jj] += qv[a]*kv;
        }
    }

    // mask (t==t' -> -5e4, unscaled), scale others by d^-0.5=0.125, per-row lse
    float lse[4];
    #pragma unroll
    for (int a = 0; a < 4; a++) {
        int r  = 4*rt + a;
        int tr = tq[r];
        float m = -1e30f;
        #pragma unroll
        for (int jj = 0; jj < 8; jj++) {
            int j = ct + 16*jj;
            float dv = (tk[j] == tr) ? NEGV : dacc[a][jj]*0.125f;
            dacc[a][jj] = dv;
            m = fmaxf(m, dv);
        }
        #pragma unroll
        for (int s = 1; s < 16; s <<= 1)
            m = fmaxf(m, __shfl_xor_sync(0xffffffffu, m, s));
        float sum = 0.f;
        #pragma unroll
        for (int jj = 0; jj < 8; jj++) sum += __expf(dacc[a][jj] - m);
        #pragma unroll
        for (int s = 1; s < 16; s <<= 1)
            sum += __shfl_xor_sync(0xffffffffu, sum, s);
        lse[a] = m + __logf(sum);
    }
    __syncthreads();   // all threads done reading ks before overwrite

    float* probs = ks;  // reuse (8320 floats >= 64*129=8256)
    #pragma unroll
    for (int a = 0; a < 4; a++) {
        int r = 4*rt + a;
        #pragma unroll
        for (int jj = 0; jj < 8; jj++)
            probs[r*P_STRIDE + ct + 16*jj] = __expf(dacc[a][jj] - lse[a]);
        if (ct == 0)
            g_logits[pbase + h*Ss + tq[r]] = lse[a];
    }
    __syncthreads();

    // bo = probs @ vs : thread owns rows 4rt+a, cols ct+16*ee
    float oacc[4][4];
    #pragma unroll
    for (int a = 0; a < 4; a++)
        #pragma unroll
        for (int e = 0; e < 4; e++) oacc[a][e] = 0.f;

    for (int j = 0; j < 128; j++) {
        float pv[4];
        #pragma unroll
        for (int a = 0; a < 4; a++) pv[a] = probs[(4*rt + a)*P_STRIDE + j];
        #pragma unroll
        for (int e = 0; e < 4; e++) {
            float vv = vs[j*64 + ct + 16*e];
            #pragma unroll
            for (int a = 0; a < 4; a++) oacc[a][e] += pv[a]*vv;
        }
    }
    #pragma unroll
    for (int a = 0; a < 4; a++) {
        int t = tq[4*rt + a];
        float* orow = g_o + ((size_t)(pbase + h*Ss + t))*Dd;
        #pragma unroll
        for (int e = 0; e < 4; e++)
            orow[ct + 16*e] = oacc[a][e];
    }
}

// ---------------- 4) combine hash rounds via softmax(logits) ----------------
__global__ void __launch_bounds__(256) combine_kernel(float* __restrict__ out)
{
    size_t gid = (size_t)blockIdx.x*256 + threadIdx.x;
    if (gid >= (size_t)Bb*Ss*Dd) return;
    int e = gid & 63;
    size_t bt = gid >> 6;
    int t = (int)(bt & (Ss - 1));
    int b = (int)(bt >> 12);

    float l[Hh];
    float m = -1e30f;
    #pragma unroll
    for (int h = 0; h < Hh; h++) {
        l[h] = g_logits[((size_t)(b*Hh + h))*Ss + t];
        m = fmaxf(m, l[h]);
    }
    float ssum = 0.f;
    #pragma unroll
    for (int h = 0; h < Hh; h++) { l[h] = __expf(l[h] - m); ssum += l[h]; }
    float inv = 1.f / ssum;
    float acc = 0.f;
    #pragma unroll
    for (int h = 0; h < Hh; h++)
        acc += l[h]*inv * g_o[(((size_t)(b*Hh + h))*Ss + t)*Dd + e];
    out[gid] = acc;
}

// ---------------- 5) buckets output (global bucket ids as float) ------------
__global__ void __launch_bounds__(256) buckets_kernel(float* __restrict__ outb)
{
    int gid = blockIdx.x*256 + threadIdx.x;
    if (gid >= Bb*Hh*Ss) return;
    int h = (gid >> 12) & 7;
    outb[gid] = (float)(g_bucket[gid] + h*NB);
}

// ---------------- launch -----------------------------------------------------
extern "C" void kernel_launch(void* const* d_in, const int* in_sizes, int n_in,
                              void* d_out, int out_size)
{
    const float* qk  = (const float*)d_in[0];
    const float* v   = (const float*)d_in[1];
    const float* rot = (const float*)d_in[2];
    float* out = (float*)d_out;

    cudaFuncSetAttribute(hash_kernel, cudaFuncAttributeMaxDynamicSharedMemorySize, HASH_SMEM);
    cudaFuncSetAttribute(attn_kernel, cudaFuncAttributeMaxDynamicSharedMemorySize, ATTN_SMEM);

    hash_kernel<<<Bb*(Ss/TT), 256, HASH_SMEM>>>(qk, rot);
    sort_kernel<<<Bb*Hh, 256>>>();
    attn_kernel<<<Bb*NCHUNK, 256, ATTN_SMEM>>>(qk, v);
    combine_kernel<<<(int)(((size_t)Bb*Ss*Dd + 255)/256), 256>>>(out);

    if (out_size >= Bb*Ss*Dd + Bb*Hh*Ss) {
        buckets_kernel<<<(Bb*Hh*Ss + 255)/256, 256>>>(out + (size_t)Bb*Ss*Dd);
    }
}

// round 3
// speedup vs baseline: 1.1438x; 1.1438x over previous
#include <cuda_runtime.h>
#include <math.h>
#include <stdint.h>

#define Bb 16
#define Ss 4096
#define Dd 64
#define Hh 8
#define NB 64          // buckets per hash
#define NCHUNK 512     // Hh * NB
#define NEGV (-50000.0f)

typedef unsigned long long ull;

// ---------------- f32x2 packed-math helpers (sm_103a FFMA2) -----------------
__device__ __forceinline__ ull ffma2(ull a, ull b, ull c) {
    ull d;
    asm("fma.rn.f32x2 %0, %1, %2, %3;" : "=l"(d) : "l"(a), "l"(b), "l"(c));
    return d;
}
__device__ __forceinline__ float f32x2_sum(ull v) {
    float lo, hi;
    asm("mov.b64 {%0, %1}, %2;" : "=f"(lo), "=f"(hi) : "l"(v));
    return lo + hi;
}
__device__ __forceinline__ ull ld64s(const float* p) {
    return *(const ull*)p;   // caller guarantees 8B alignment
}

// ---------------- device scratch (static globals: no runtime allocation) ----
__device__ int   g_bucket[Bb*Hh*Ss];     // local bucket id 0..63 per (b,h,t)
__device__ int   g_perm  [Bb*Hh*Ss];     // sorted rank -> t  (per (b,h) segment)
__device__ float g_o     [(size_t)Bb*Hh*Ss*Dd]; // per-hash outputs
__device__ float g_logits[Bb*Hh*Ss];     // per-hash lse

// ---------------- 1) LSH hashing (EXACT sequential accumulation: argmax is
// discontinuous, so the reduction order must match the passing round-1 code) -
#define TT 16
#define HASH_SMEM ((64*256 + TT*64) * 4)
__global__ void __launch_bounds__(256) hash_kernel(
    const float* __restrict__ qk, const float* __restrict__ rot)
{
    extern __shared__ float sm[];
    float* rotS = sm;              // [64][256]  (f major, hi = tid)
    float* qs   = sm + 64*256;     // [TT][64]

    int blocksPerB = Ss / TT;                 // 256
    int b  = blockIdx.x / blocksPerB;
    int t0 = (blockIdx.x % blocksPerB) * TT;
    int tid = threadIdx.x;

    const float* rb = rot + (size_t)b * 64 * 256;
    for (int f = 0; f < 64; f++)
        rotS[f*256 + tid] = rb[f*256 + tid];
    for (int idx = tid; idx < TT*64; idx += 256)
        qs[idx] = qk[((size_t)b*Ss + t0 + (idx >> 6))*Dd + (idx & 63)];
    __syncthreads();

    float acc[TT];
    #pragma unroll
    for (int i = 0; i < TT; i++) acc[i] = 0.f;
    for (int f = 0; f < 64; f++) {
        float rv = rotS[f*256 + tid];
        #pragma unroll
        for (int i = 0; i < TT; i++) acc[i] += qs[i*64 + f] * rv;
    }

    int lane = tid & 31;
    int h    = tid >> 5;            // warp w handles hash w
    #pragma unroll
    for (int i = 0; i < TT; i++) {
        float v = acc[i];
        float val; int idx;
        if (v >= -v) { val = v;  idx = lane; }        // tie (v==0) -> first idx
        else         { val = -v; idx = lane + 32; }
        #pragma unroll
        for (int m = 16; m > 0; m >>= 1) {
            float ov = __shfl_xor_sync(0xffffffffu, val, m);
            int   oi = __shfl_xor_sync(0xffffffffu, idx, m);
            if (ov > val || (ov == val && oi < idx)) { val = ov; idx = oi; }
        }
        if (lane == 0)
            g_bucket[((size_t)b*Hh + h)*Ss + t0 + i] = idx;
    }
}

// ---------------- 2) stable counting sort per (b,h) -------------------------
__global__ void __launch_bounds__(256) sort_kernel()
{
    __shared__ int sb[Ss];
    __shared__ int cnt[NB];
    __shared__ int offs[NB + 1];
    int bh  = blockIdx.x;           // b*Hh + h
    int tid = threadIdx.x;
    const int base = bh * Ss;

    for (int i = tid; i < NB; i += 256) cnt[i] = 0;
    __syncthreads();
    for (int i = tid; i < Ss; i += 256) {
        int v = g_bucket[base + i];
        sb[i] = v;
        atomicAdd(&cnt[v], 1);
    }
    __syncthreads();
    if (tid == 0) {
        offs[0] = 0;
        for (int k = 0; k < NB; k++) offs[k+1] = offs[k] + cnt[k];
    }
    __syncthreads();
    if (tid < NB) {                 // thread = bucket; stable in t order
        int w = tid, pos = offs[w];
        for (int t = 0; t < Ss; t++)
            if (sb[t] == w) g_perm[base + pos++] = t;
    }
}

// ---------------- 3) chunked attention + scatter ----------------------------
#define KS_STRIDE 66
#define P_STRIDE 130
#define V_STRIDE 134
#define ATTN_SMEM ((64*KS_STRIDE + 128*KS_STRIDE + 64*V_STRIDE) * 4 + 192 * 4)
__global__ void __launch_bounds__(256) attn_kernel(
    const float* __restrict__ qk, const float* __restrict__ v)
{
    extern __shared__ float sm[];
    float* qs  = sm;                          // [64][66] raw q
    float* ks  = qs + 64*KS_STRIDE;           // [128][66] normalized k; reused as probs[64][130]
    float* vst = ks + 128*KS_STRIDE;          // transposed V: [64 cols][134] (+ per-col offset)
    int*   tq  = (int*)(vst + 64*V_STRIDE);   // [64]
    int*   tk  = tq + 64;                     // [128]

    int b = blockIdx.x >> 9;
    int c = blockIdx.x & (NCHUNK - 1);
    int h = c >> 6;
    int cprev = (c + NCHUNK - 1) & (NCHUNK - 1);
    int tid = threadIdx.x;
    const int pbase = b * (Hh * Ss);

    if (tid < 64) {
        tq[tid] = g_perm[pbase + c*64 + tid];
    } else if (tid < 192) {
        int j = tid - 64;
        tk[j] = (j < 64) ? g_perm[pbase + c*64 + j]
                         : g_perm[pbase + cprev*64 + (j - 64)];
    }
    __syncthreads();

    const float* qkb = qk + (size_t)b*Ss*Dd;
    const float* vb  = v  + (size_t)b*Ss*Dd;

    for (int idx = tid; idx < 64*16; idx += 256) {
        int r = idx >> 4, q4 = idx & 15;
        float4 x = *(const float4*)(qkb + (size_t)tq[r]*Dd + q4*4);
        float* d = qs + r*KS_STRIDE + q4*4;
        d[0]=x.x; d[1]=x.y; d[2]=x.z; d[3]=x.w;
    }
    for (int idx = tid; idx < 128*16; idx += 256) {
        int r = idx >> 4, q4 = idx & 15;
        float4 x = *(const float4*)(qkb + (size_t)tk[r]*Dd + q4*4);
        float* d = ks + r*KS_STRIDE + q4*4;
        d[0]=x.x; d[1]=x.y; d[2]=x.z; d[3]=x.w;
        // V transposed: element (row j=r, col c) -> vst[c*134 + g(c) + r]
        float4 y = *(const float4*)(vb + (size_t)tk[r]*Dd + q4*4);
        int c0 = q4*4;
        vst[(c0+0)*V_STRIDE + 2*(((c0+0)>>4)&3) + r] = y.x;
        vst[(c0+1)*V_STRIDE + 2*(((c0+1)>>4)&3) + r] = y.y;
        vst[(c0+2)*V_STRIDE + 2*(((c0+2)>>4)&3) + r] = y.z;
        vst[(c0+3)*V_STRIDE + 2*(((c0+3)>>4)&3) + r] = y.w;
    }
    __syncthreads();

    // normalize k rows (make_unit_length: x / (||x|| + 1e-6))
    if (tid < 128) {
        float* row = ks + tid*KS_STRIDE;
        ull s2 = 0ull;
        #pragma unroll
        for (int f = 0; f < 64; f += 2) {
            ull x = ld64s(row + f);
            s2 = ffma2(x, x, s2);
        }
        float ssq = f32x2_sum(s2);
        float inv = 1.0f / (sqrtf(ssq) + 1e-6f);
        #pragma unroll
        for (int f = 0; f < 64; f++) row[f] *= inv;
    }
    __syncthreads();

    // dots[64][128]: thread (rt,ct) owns rows 4rt+a, cols ct+16*jj (f packed)
    int rt = tid >> 4;
    int ct = tid & 15;
    ull dacc2[4][8];
    #pragma unroll
    for (int a = 0; a < 4; a++)
        #pragma unroll
        for (int jj = 0; jj < 8; jj++) dacc2[a][jj] = 0ull;

    #pragma unroll 2
    for (int f = 0; f < 64; f += 2) {
        ull qv2[4];
        #pragma unroll
        for (int a = 0; a < 4; a++) qv2[a] = ld64s(qs + (4*rt + a)*KS_STRIDE + f);
        #pragma unroll
        for (int jj = 0; jj < 8; jj++) {
            ull kv2 = ld64s(ks + (ct + 16*jj)*KS_STRIDE + f);
            #pragma unroll
            for (int a = 0; a < 4; a++)
                dacc2[a][jj] = ffma2(qv2[a], kv2, dacc2[a][jj]);
        }
    }

    float dacc[4][8];
    #pragma unroll
    for (int a = 0; a < 4; a++)
        #pragma unroll
        for (int jj = 0; jj < 8; jj++) dacc[a][jj] = f32x2_sum(dacc2[a][jj]);

    // mask (t==t' -> -5e4, unscaled), scale others by d^-0.5=0.125, per-row lse
    float lse[4];
    #pragma unroll
    for (int a = 0; a < 4; a++) {
        int r  = 4*rt + a;
        int tr = tq[r];
        float m = -1e30f;
        #pragma unroll
        for (int jj = 0; jj < 8; jj++) {
            int j = ct + 16*jj;
            float dv = (tk[j] == tr) ? NEGV : dacc[a][jj]*0.125f;
            dacc[a][jj] = dv;
            m = fmaxf(m, dv);
        }
        #pragma unroll
        for (int s = 1; s < 16; s <<= 1)
            m = fmaxf(m, __shfl_xor_sync(0xffffffffu, m, s));
        float sum = 0.f;
        #pragma unroll
        for (int jj = 0; jj < 8; jj++) sum += __expf(dacc[a][jj] - m);
        #pragma unroll
        for (int s = 1; s < 16; s <<= 1)
            sum += __shfl_xor_sync(0xffffffffu, sum, s);
        lse[a] = m + __logf(sum);
    }
    __syncthreads();   // all threads done reading ks before overwrite

    float* probs = ks;  // reuse (128*66 >= 64*130)
    #pragma unroll
    for (int a = 0; a < 4; a++) {
        int r = 4*rt + a;
        #pragma unroll
        for (int jj = 0; jj < 8; jj++)
            probs[r*P_STRIDE + ct + 16*jj] = __expf(dacc[a][jj] - lse[a]);
        if (ct == 0)
            g_logits[pbase + h*Ss + tq[r]] = lse[a];
    }
    __syncthreads();

    // bo = probs @ V : thread owns rows 4rt+a, cols ct+16*e; packed over j
    ull oacc2[4][4];
    #pragma unroll
    for (int a = 0; a < 4; a++)
        #pragma unroll
        for (int e = 0; e < 4; e++) oacc2[a][e] = 0ull;

    const float* vcol[4];
    #pragma unroll
    for (int e = 0; e < 4; e++)
        vcol[e] = vst + (ct + 16*e)*V_STRIDE + 2*e;   // g(ct+16e) = 2e

    #pragma unroll 2
    for (int j = 0; j < 128; j += 2) {
        ull pv2[4];
        #pragma unroll
        for (int a = 0; a < 4; a++) pv2[a] = ld64s(probs + (4*rt + a)*P_STRIDE + j);
        #pragma unroll
        for (int e = 0; e < 4; e++) {
            ull vv2 = ld64s(vcol[e] + j);
            #pragma unroll
            for (int a = 0; a < 4; a++)
                oacc2[a][e] = ffma2(pv2[a], vv2, oacc2[a][e]);
        }
    }
    #pragma unroll
    for (int a = 0; a < 4; a++) {
        int t = tq[4*rt + a];
        float* orow = g_o + ((size_t)(pbase + h*Ss + t))*Dd;
        #pragma unroll
        for (int e = 0; e < 4; e++)
            orow[ct + 16*e] = f32x2_sum(oacc2[a][e]);
    }
}

// ---------------- 4) combine hash rounds via softmax(logits) ----------------
__global__ void __launch_bounds__(256) combine_kernel(float* __restrict__ out)
{
    size_t gid = (size_t)blockIdx.x*256 + threadIdx.x;   // one float4 per thread
    if (gid >= (size_t)Bb*Ss*Dd/4) return;
    int e4 = (int)(gid & 15);
    size_t bt = gid >> 4;
    int t = (int)(bt & (Ss - 1));
    int b = (int)(bt >> 12);

    float l[Hh];
    float m = -1e30f;
    #pragma unroll
    for (int h = 0; h < Hh; h++) {
        l[h] = g_logits[((size_t)(b*Hh + h))*Ss + t];
        m = fmaxf(m, l[h]);
    }
    float ssum = 0.f;
    #pragma unroll
    for (int h = 0; h < Hh; h++) { l[h] = __expf(l[h] - m); ssum += l[h]; }
    float inv = 1.f / ssum;

    float4 acc = make_float4(0.f, 0.f, 0.f, 0.f);
    #pragma unroll
    for (int h = 0; h < Hh; h++) {
        float w = l[h]*inv;
        float4 o = *(const float4*)(g_o + (((size_t)(b*Hh + h))*Ss + t)*Dd + e4*4);
        acc.x += w*o.x; acc.y += w*o.y; acc.z += w*o.z; acc.w += w*o.w;
    }
    *(float4*)(out + gid*4) = acc;
}

// ---------------- 5) buckets output (global bucket ids as float) ------------
__global__ void __launch_bounds__(256) buckets_kernel(float* __restrict__ outb)
{
    int gid = blockIdx.x*256 + threadIdx.x;
    if (gid >= Bb*Hh*Ss) return;
    int h = (gid >> 12) & 7;
    outb[gid] = (float)(g_bucket[gid] + h*NB);
}

// ---------------- launch -----------------------------------------------------
extern "C" void kernel_launch(void* const* d_in, const int* in_sizes, int n_in,
                              void* d_out, int out_size)
{
    const float* qk  = (const float*)d_in[0];
    const float* v   = (const float*)d_in[1];
    const float* rot = (const float*)d_in[2];
    float* out = (float*)d_out;

    cudaFuncSetAttribute(hash_kernel, cudaFuncAttributeMaxDynamicSharedMemorySize, HASH_SMEM);
    cudaFuncSetAttribute(attn_kernel, cudaFuncAttributeMaxDynamicSharedMemorySize, ATTN_SMEM);

    hash_kernel<<<Bb*(Ss/TT), 256, HASH_SMEM>>>(qk, rot);
    sort_kernel<<<Bb*Hh, 256>>>();
    attn_kernel<<<Bb*NCHUNK, 256, ATTN_SMEM>>>(qk, v);
    combine_kernel<<<(int)(((size_t)Bb*Ss*Dd/4 + 255)/256), 256>>>(out);

    if (out_size >= Bb*Ss*Dd + Bb*Hh*Ss) {
        buckets_kernel<<<(Bb*Hh*Ss + 255)/256, 256>>>(out + (size_t)Bb*Ss*Dd);
    }
}